// round 4
// baseline (speedup 1.0000x reference)
#include <cuda_runtime.h>

#define HW    2048
#define HW2   1024
#define MASK  2047
#define BATCH 4
#define SY    32
#define WPB   5
#define NSTRIP 35          // 35*60 = 2100 >= 2048; overlap strips write identical wrapped values

// folded constants
#define C0f     0.3623577545f      // cos(1.2)
#define S0f     0.9320390860f      // sin(1.2)
#define EPBf    0.19245009f        // EB  * sqrt(KB),  KB = (DT/TAU)/dx^2
#define EPDf    0.0038490018f      // EBD * sqrt(KB)
#define PCCf    (-0.0057735027f)   // M6EBD * KA / sqrt(KB),  KA = (DT/TAU)/(2dx)^2
#define KTf     0.1111111111f      // DT/dx^2
#define KAPf    1.8f
#define DTTAUf  0.3333333333f
#define APIXf   0.2864788976f      // alpha/pi
#define PIO2f   1.5707963268f

// stage1: P1/P2 pre-scaled by KA, E2 pre-scaled by KB (via eps' = eps*sqrt(KB))
__device__ __forceinline__ void stage1(float L, float R, float dn, float up,
                                       float& P1, float& P2, float& E2)
{
    float dx  = R - L;
    float dy  = up - dn;
    float dx2 = dx * dx;
    float r2  = fmaf(dy, dy, dx2);
    float a2  = fmaf(-dy, dy, dx2);
    float b2  = 2.0f * dx * dy;
    float a3  = fmaf(a2, dx, -(b2 * dy));
    float b3  = fmaf(a2, dy,  (b2 * dx));
    float Az  = fmaf(a3, a3, -(b3 * b3));
    float Bz  = 2.0f * a3 * b3;
    float r6  = r2 * r2 * r2;
    float ir6 = __fdividef(1.0f, fmaxf(r6, 1e-30f));
    float u   = fmaf(Az, C0f,  (Bz * S0f)) * ir6;
    float v   = fmaf(Bz, C0f, -(Az * S0f)) * ir6;
    float ep  = fmaf(EPDf, u, EPBf);        // eps * sqrt(KB)
    float pc  = ep * (PCCf * v);            // eps*eps_deriv*KA (grid consts folded)
    P1 =  pc * dx;
    P2 = -pc * dy;
    E2 = ep * ep;                           // eps^2 * KB
}

__device__ __forceinline__ float atan_pos(float g)
{
    float inv = __fdividef(1.0f, g);
    bool  big = g > 1.0f;
    float w   = big ? inv : g;
    float w2  = w * w;
    float p   = fmaf(w2, -0.01172120f, 0.05265332f);
    p = fmaf(w2, p, -0.11643287f);
    p = fmaf(w2, p,  0.19354346f);
    p = fmaf(w2, p, -0.33262347f);
    p = fmaf(w2, p,  0.99997726f);
    p = p * w;
    return big ? (PIO2f - p) : p;
}

template<bool WRAP>
__device__ __forceinline__ void sweep_body(const float* __restrict__ phi,
                                           const float* __restrict__ tempr,
                                           float* __restrict__ out,
                                           int y0)
{
    const unsigned FULL = 0xffffffffu;
    const int lane  = threadIdx.x & 31;
    const int wid   = threadIdx.x >> 5;
    const int strip = blockIdx.x * WPB + wid;       // 0..34
    const int b     = blockIdx.z;
    const int lm    = lane - 1;
    const int lp    = lane + 1;

    const int xc = (strip * 60 - 2 + 2 * lane) & MASK;
    const size_t base = (size_t)b * HW * HW;
    const float2* __restrict__ pb = (const float2*)(phi   + base) + (xc >> 1);
    const float2* __restrict__ tb = (const float2*)(tempr + base) + (xc >> 1);
    float2* __restrict__ po = (float2*)(out + base) + (xc >> 1);
    float2* __restrict__ to = (float2*)(out + (size_t)BATCH * HW * HW + base) + (xc >> 1);

#define PROW(r) pb[((r) & MASK) * HW2]
#define TROW(r) tb[((r) & MASK) * HW2]

    // prologue (wrap-safe via mask; cheap, one-time)
    float2 pm2 = PROW(y0 - 2), pm1 = PROW(y0 - 1), p0 = PROW(y0);
    float2 pp1 = PROW(y0 + 1), pp2 = PROW(y0 + 2), pp3 = PROW(y0 + 3);
    float2 tm1 = TROW(y0 - 1), t0 = TROW(y0);
    float2 tp1 = TROW(y0 + 1), tp2 = TROW(y0 + 2);

    float2 P1m, P1c, P2c, E2c;
    {
        float Lc = __shfl_sync(FULL, pm1.y, lm);
        float Rc = __shfl_sync(FULL, pm1.x, lp);
        float d0, d1;
        stage1(Lc,    pm1.y, pm2.x, p0.x, P1m.x, d0, d1);
        stage1(pm1.x, Rc,    pm2.y, p0.y, P1m.y, d0, d1);
    }
    {
        float Lc = __shfl_sync(FULL, p0.y, lm);
        float Rc = __shfl_sync(FULL, p0.x, lp);
        stage1(Lc,   p0.y, pm1.x, pp1.x, P1c.x, P2c.x, E2c.x);
        stage1(p0.x, Rc,   pm1.y, pp1.y, P1c.y, P2c.y, E2c.y);
    }

    const bool wr = (lane >= 1) && (lane <= 30);

    // marching pointers (interior fast path: no mask, no per-iter index math)
    const float2* pld = pb + (size_t)(y0 + 4) * HW2;
    const float2* tld = tb + (size_t)(y0 + 3) * HW2;
    float2* por = po + (size_t)y0 * HW2;
    float2* tor = to + (size_t)y0 * HW2;

    #pragma unroll 4
    for (int i = 0; i < SY; ++i) {
        float2 pp4, tp3;
        if (WRAP) {
            pp4 = PROW(y0 + i + 4);
            tp3 = TROW(y0 + i + 3);
        } else {
            pp4 = *pld;  pld += HW2;
            tp3 = *tld;  tld += HW2;
        }

        float2 P1n, P2n, E2n;
        {
            float Lc = __shfl_sync(FULL, pp1.y, lm);
            float Rc = __shfl_sync(FULL, pp1.x, lp);
            stage1(Lc,    pp1.y, p0.x, pp2.x, P1n.x, P2n.x, E2n.x);
            stage1(pp1.x, Rc,    p0.y, pp2.y, P1n.y, P2n.y, E2n.y);
        }

        float Lp  = __shfl_sync(FULL, p0.y,  lm);
        float Rp  = __shfl_sync(FULL, p0.x,  lp);
        float Lt  = __shfl_sync(FULL, t0.y,  lm);
        float Rt  = __shfl_sync(FULL, t0.x,  lp);
        float LP2 = __shfl_sync(FULL, P2c.y, lm);
        float RP2 = __shfl_sync(FULL, P2c.x, lp);

        float2 outp, outt;
        {   // column xc
            float lapp = (pp1.x + pm1.x) + (Lp + p0.y);
            lapp = fmaf(p0.x, -4.0f, lapp);
            float lapt = (tp1.x + tm1.x) + (Lt + t0.y);
            lapt = fmaf(t0.x, -4.0f, lapt);
            float term = (P1n.x - P1m.x) + (P2c.y - LP2);   // KA pre-folded
            float at   = atan_pos(fmaf(t0.x, -10.0f, 10.0f));
            float marg = fmaf(APIXf, at, p0.x - 0.5f);
            float q    = fmaf(-p0.x, p0.x, p0.x);
            float dphi = fmaf(E2c.x, lapp, term);           // KB pre-folded
            dphi = fmaf(q * marg, DTTAUf, dphi);
            outp.x = p0.x + dphi;
            outt.x = fmaf(KAPf, dphi, fmaf(KTf, lapt, t0.x));
        }
        {   // column xc+1
            float lapp = (pp1.y + pm1.y) + (p0.x + Rp);
            lapp = fmaf(p0.y, -4.0f, lapp);
            float lapt = (tp1.y + tm1.y) + (t0.x + Rt);
            lapt = fmaf(t0.y, -4.0f, lapt);
            float term = (P1n.y - P1m.y) + (RP2 - P2c.x);
            float at   = atan_pos(fmaf(t0.y, -10.0f, 10.0f));
            float marg = fmaf(APIXf, at, p0.y - 0.5f);
            float q    = fmaf(-p0.y, p0.y, p0.y);
            float dphi = fmaf(E2c.y, lapp, term);
            dphi = fmaf(q * marg, DTTAUf, dphi);
            outp.y = p0.y + dphi;
            outt.y = fmaf(KAPf, dphi, fmaf(KTf, lapt, t0.y));
        }

        if (wr) {
            *por = outp;
            *tor = outt;
        }
        por += HW2;
        tor += HW2;

        pm1 = p0;  p0 = pp1;  pp1 = pp2;  pp2 = pp3;  pp3 = pp4;
        tm1 = t0;  t0 = tp1;  tp1 = tp2;  tp2 = tp3;
        P1m = P1c; P1c = P1n; P2c = P2n; E2c = E2n;
    }
#undef PROW
#undef TROW
}

__global__ __launch_bounds__(WPB * 32, 5)
void dendrite_interior(const float* __restrict__ phi,
                       const float* __restrict__ tempr,
                       float* __restrict__ out)
{
    // y-blocks 1..62 never wrap in y
    sweep_body<false>(phi, tempr, out, (blockIdx.y + 1) * SY);
}

__global__ __launch_bounds__(WPB * 32, 5)
void dendrite_edge(const float* __restrict__ phi,
                   const float* __restrict__ tempr,
                   float* __restrict__ out)
{
    // y-blocks 0 and 63 wrap
    sweep_body<true>(phi, tempr, out, (blockIdx.y ? (HW / SY - 1) : 0) * SY);
}

extern "C" void kernel_launch(void* const* d_in, const int* in_sizes, int n_in,
                              void* d_out, int out_size)
{
    const float* phi   = (const float*)d_in[0];
    const float* tempr = (const float*)d_in[1];
    float* out = (float*)d_out;

    dim3 block(WPB * 32);
    dim3 gi(NSTRIP / WPB, HW / SY - 2, BATCH);   // (7, 62, 4)
    dim3 ge(NSTRIP / WPB, 2,            BATCH);  // (7, 2, 4)
    dendrite_interior<<<gi, block>>>(phi, tempr, out);
    dendrite_edge<<<ge, block>>>(phi, tempr, out);
}

// round 5
// speedup vs baseline: 1.1747x; 1.1747x over previous
#include <cuda_runtime.h>

#define HW    2048
#define HW2   1024
#define MASK  2047
#define BATCH 4
#define SY    32
#define WPB   5
#define NSTRIP 35          // 35*60 = 2100 >= 2048; overlap strips write identical wrapped values
#define NBY   (HW / SY)    // 64

// folded constants
#define C0f     0.3623577545f      // cos(1.2)
#define S0f     0.9320390860f      // sin(1.2)
#define EPBf    0.19245009f        // EB  * sqrt(KB),  KB = (DT/TAU)/dx^2
#define EPDf    0.0038490018f      // EBD * sqrt(KB)
#define PCCf    (-0.0057735027f)   // M6EBD * KA / sqrt(KB),  KA = (DT/TAU)/(2dx)^2
#define KTf     0.1111111111f      // DT/dx^2
#define KAPf    1.8f
#define DTTAUf  0.3333333333f
#define APIXf   0.2864788976f      // alpha/pi
#define PIO2f   1.5707963268f

// stage1: P1/P2 pre-scaled by KA, E2 pre-scaled by KB (via eps' = eps*sqrt(KB))
__device__ __forceinline__ void stage1(float L, float R, float dn, float up,
                                       float& P1, float& P2, float& E2)
{
    float dx  = R - L;
    float dy  = up - dn;
    float dx2 = dx * dx;
    float r2  = fmaf(dy, dy, dx2);
    float a2  = fmaf(-dy, dy, dx2);
    float b2  = 2.0f * dx * dy;
    float a3  = fmaf(a2, dx, -(b2 * dy));
    float b3  = fmaf(a2, dy,  (b2 * dx));
    float Az  = fmaf(a3, a3, -(b3 * b3));
    float Bz  = 2.0f * a3 * b3;
    float r6  = r2 * r2 * r2;
    float ir6 = __fdividef(1.0f, fmaxf(r6, 1e-30f));
    float u   = fmaf(Az, C0f,  (Bz * S0f)) * ir6;
    float v   = fmaf(Bz, C0f, -(Az * S0f)) * ir6;
    float ep  = fmaf(EPDf, u, EPBf);        // eps * sqrt(KB)
    float pc  = ep * (PCCf * v);            // eps*eps_deriv*KA
    P1 =  pc * dx;
    P2 = -pc * dy;
    E2 = ep * ep;                           // eps^2 * KB
}

__device__ __forceinline__ float atan_pos(float g)
{
    float inv = __fdividef(1.0f, g);
    bool  big = g > 1.0f;
    float w   = big ? inv : g;
    float w2  = w * w;
    float p   = fmaf(w2, -0.01172120f, 0.05265332f);
    p = fmaf(w2, p, -0.11643287f);
    p = fmaf(w2, p,  0.19354346f);
    p = fmaf(w2, p, -0.33262347f);
    p = fmaf(w2, p,  0.99997726f);
    p = p * w;
    return big ? (PIO2f - p) : p;
}

template<bool WRAP>
__device__ __forceinline__ void sweep_body(const float* __restrict__ phi,
                                           const float* __restrict__ tempr,
                                           float* __restrict__ out,
                                           int y0)
{
    const unsigned FULL = 0xffffffffu;
    const int lane  = threadIdx.x & 31;
    const int wid   = threadIdx.x >> 5;
    const int strip = blockIdx.x * WPB + wid;       // 0..34
    const int b     = blockIdx.z;
    const int lm    = lane - 1;
    const int lp    = lane + 1;

    const int xc = (strip * 60 - 2 + 2 * lane) & MASK;
    const size_t base = (size_t)b * HW * HW;
    const float2* __restrict__ pb = (const float2*)(phi   + base) + (xc >> 1);
    const float2* __restrict__ tb = (const float2*)(tempr + base) + (xc >> 1);
    float2* __restrict__ po = (float2*)(out + base) + (xc >> 1);
    float2* __restrict__ to = (float2*)(out + (size_t)BATCH * HW * HW + base) + (xc >> 1);

#define PROW(r) pb[((r) & MASK) * HW2]
#define TROW(r) tb[((r) & MASK) * HW2]

    // prologue (wrap-safe via mask; one-time)
    float2 pm2 = PROW(y0 - 2), pm1 = PROW(y0 - 1), p0 = PROW(y0);
    float2 pp1 = PROW(y0 + 1), pp2 = PROW(y0 + 2), pp3 = PROW(y0 + 3);
    float2 tm1 = TROW(y0 - 1), t0 = TROW(y0);
    float2 tp1 = TROW(y0 + 1), tp2 = TROW(y0 + 2);

    float2 P1m, P1c, P2c, E2c;
    {
        float Lc = __shfl_sync(FULL, pm1.y, lm);
        float Rc = __shfl_sync(FULL, pm1.x, lp);
        float d0, d1;
        stage1(Lc,    pm1.y, pm2.x, p0.x, P1m.x, d0, d1);
        stage1(pm1.x, Rc,    pm2.y, p0.y, P1m.y, d0, d1);
    }
    {
        float Lc = __shfl_sync(FULL, p0.y, lm);
        float Rc = __shfl_sync(FULL, p0.x, lp);
        stage1(Lc,   p0.y, pm1.x, pp1.x, P1c.x, P2c.x, E2c.x);
        stage1(p0.x, Rc,   pm1.y, pp1.y, P1c.y, P2c.y, E2c.y);
    }

    const bool wr = (lane >= 1) && (lane <= 30);

    // marching pointers (interior path: no mask, no per-iter index math)
    const float2* pld = pb + (size_t)(y0 + 4) * HW2;
    const float2* tld = tb + (size_t)(y0 + 3) * HW2;
    float2* por = po + (size_t)y0 * HW2;
    float2* tor = to + (size_t)y0 * HW2;

    #pragma unroll 4
    for (int i = 0; i < SY; ++i) {
        float2 pp4, tp3;
        if (WRAP) {
            pp4 = PROW(y0 + i + 4);
            tp3 = TROW(y0 + i + 3);
        } else {
            pp4 = *pld;  pld += HW2;
            tp3 = *tld;  tld += HW2;
        }

        float2 P1n, P2n, E2n;
        {
            float Lc = __shfl_sync(FULL, pp1.y, lm);
            float Rc = __shfl_sync(FULL, pp1.x, lp);
            stage1(Lc,    pp1.y, p0.x, pp2.x, P1n.x, P2n.x, E2n.x);
            stage1(pp1.x, Rc,    p0.y, pp2.y, P1n.y, P2n.y, E2n.y);
        }

        float Lp  = __shfl_sync(FULL, p0.y,  lm);
        float Rp  = __shfl_sync(FULL, p0.x,  lp);
        float Lt  = __shfl_sync(FULL, t0.y,  lm);
        float Rt  = __shfl_sync(FULL, t0.x,  lp);
        float LP2 = __shfl_sync(FULL, P2c.y, lm);
        float RP2 = __shfl_sync(FULL, P2c.x, lp);

        float2 outp, outt;
        {   // column xc
            float lapp = (pp1.x + pm1.x) + (Lp + p0.y);
            lapp = fmaf(p0.x, -4.0f, lapp);
            float lapt = (tp1.x + tm1.x) + (Lt + t0.y);
            lapt = fmaf(t0.x, -4.0f, lapt);
            float term = (P1n.x - P1m.x) + (P2c.y - LP2);   // KA pre-folded
            float at   = atan_pos(fmaf(t0.x, -10.0f, 10.0f));
            float marg = fmaf(APIXf, at, p0.x - 0.5f);
            float q    = fmaf(-p0.x, p0.x, p0.x);
            float dphi = fmaf(E2c.x, lapp, term);           // KB pre-folded
            dphi = fmaf(q * marg, DTTAUf, dphi);
            outp.x = p0.x + dphi;
            outt.x = fmaf(KAPf, dphi, fmaf(KTf, lapt, t0.x));
        }
        {   // column xc+1
            float lapp = (pp1.y + pm1.y) + (p0.x + Rp);
            lapp = fmaf(p0.y, -4.0f, lapp);
            float lapt = (tp1.y + tm1.y) + (t0.x + Rt);
            lapt = fmaf(t0.y, -4.0f, lapt);
            float term = (P1n.y - P1m.y) + (RP2 - P2c.x);
            float at   = atan_pos(fmaf(t0.y, -10.0f, 10.0f));
            float marg = fmaf(APIXf, at, p0.y - 0.5f);
            float q    = fmaf(-p0.y, p0.y, p0.y);
            float dphi = fmaf(E2c.y, lapp, term);
            dphi = fmaf(q * marg, DTTAUf, dphi);
            outp.y = p0.y + dphi;
            outt.y = fmaf(KAPf, dphi, fmaf(KTf, lapt, t0.y));
        }

        if (wr) {
            *por = outp;
            *tor = outt;
        }
        por += HW2;
        tor += HW2;

        pm1 = p0;  p0 = pp1;  pp1 = pp2;  pp2 = pp3;  pp3 = pp4;
        tm1 = t0;  t0 = tp1;  tp1 = tp2;  tp2 = tp3;
        P1m = P1c; P1c = P1n; P2c = P2n; E2c = E2n;
    }
#undef PROW
#undef TROW
}

__global__ __launch_bounds__(WPB * 32, 5)
void dendrite_sweep3(const float* __restrict__ phi,
                     const float* __restrict__ tempr,
                     float* __restrict__ out)
{
    const int by = blockIdx.y;
    const int y0 = by * SY;
    // uniform per-CTA branch: only first/last y-blocks can wrap in y
    if (by == 0 || by == NBY - 1) {
        sweep_body<true>(phi, tempr, out, y0);
    } else {
        sweep_body<false>(phi, tempr, out, y0);
    }
}

extern "C" void kernel_launch(void* const* d_in, const int* in_sizes, int n_in,
                              void* d_out, int out_size)
{
    const float* phi   = (const float*)d_in[0];
    const float* tempr = (const float*)d_in[1];
    float* out = (float*)d_out;

    dim3 block(WPB * 32);
    dim3 grid(NSTRIP / WPB, NBY, BATCH);   // (7, 64, 4) = 1792 CTAs
    dendrite_sweep3<<<grid, block>>>(phi, tempr, out);
}